// round 4
// baseline (speedup 1.0000x reference)
#include <cuda_runtime.h>
#include <math.h>

#define NN 100000
#define EE 1600000

// -------- scratch (device globals; no allocation allowed) --------
__device__ float g_cnt[NN];
__device__ float g_agg[(size_t)NN * 128];
__device__ float g_h1[(size_t)NN * 128];
__device__ float g_h2[(size_t)NN * 128];

// -------- helpers --------
__device__ __forceinline__ void red_add_v4(float* addr, float4 v) {
    asm volatile("red.global.add.v4.f32 [%0], {%1,%2,%3,%4};"
                 :: "l"(addr), "f"(v.x), "f"(v.y), "f"(v.z), "f"(v.w) : "memory");
}
__device__ __forceinline__ void red_add_f32(float* addr, float v) {
    asm volatile("red.global.add.f32 [%0], %1;" :: "l"(addr), "f"(v) : "memory");
}
__device__ __forceinline__ float sigmoidf_(float x) {
    return 1.0f / (1.0f + __expf(-x));
}

// -------- zero --------
__global__ void zero_kernel(float4* __restrict__ p, int n4) {
    int i = blockIdx.x * blockDim.x + threadIdx.x;
    int stride = gridDim.x * blockDim.x;
    float4 z = make_float4(0.f, 0.f, 0.f, 0.f);
    for (; i < n4; i += stride) p[i] = z;
}

// -------- edge scatter: per-thread = (edge, 16-float chunk) --------
// edge_index is INT32 (JAX x64 disabled truncates the reference's int64).
template<int D>   // feature width: 64 or 128
__global__ void __launch_bounds__(256) scatter_kernel(
    const int* __restrict__ ei,         // [2, E] int32
    const float* __restrict__ x,        // [N, D]
    float* __restrict__ agg,            // [N, D]
    float* __restrict__ cnt,            // [N]
    int E, int nNodes, int doCnt)
{
    const int CH = D / 16;
    long long tid = (long long)blockIdx.x * blockDim.x + threadIdx.x;
    long long e = tid / CH;
    int c = (int)(tid - e * CH);
    if (e >= E) return;
    int s = ei[e];
    int d = ei[(long long)E + e];
    if ((unsigned)s >= (unsigned)nNodes || (unsigned)d >= (unsigned)nNodes) return;
    const float4* src = (const float4*)(x + (size_t)s * D + c * 16);
    float* dst = agg + (size_t)d * D + c * 16;
    float4 a = src[0], b = src[1], cc = src[2], dd = src[3];
    red_add_v4(dst + 0, a);
    red_add_v4(dst + 4, b);
    red_add_v4(dst + 8, cc);
    red_add_v4(dst + 12, dd);
    if (doCnt && c == 0) red_add_f32(cnt + d, 1.0f);
}

// -------- combine: X = concat(self, agg/max(cnt,1)) [K]; out = sigmoid(X @ W + b) [128] --------
// 64 nodes per block, 256 threads: thread t -> node t&63, output quarter (t>>6)*32
template<int K>
__global__ void __launch_bounds__(256) combine_kernel(
    const float* __restrict__ self,   // [N, K/2]
    const float* __restrict__ agg,    // [N, K/2]
    const float* __restrict__ cnt,    // [N]
    const float* __restrict__ W,      // [K, 128] row-major
    const float* __restrict__ b,      // [128]
    float* __restrict__ out,          // [N, 128]
    int nNodes)
{
    constexpr int SELF = K / 2;
    constexpr int NP = 65;   // padded node stride for Xs (transposed)
    extern __shared__ float smf[];
    float* Xs = smf;               // K * NP
    float* Ws = smf + K * NP;      // K * 128

    const int t = threadIdx.x;
    const int base = blockIdx.x * 64;

    // Load W cooperatively (float4)
    {
        const float4* Wg = (const float4*)W;
        float4* Ws4 = (float4*)Ws;
        for (int i = t; i < K * 32; i += 256) Ws4[i] = Wg[i];
    }
    // Build X tile, transposed: Xs[k][n]
    for (int i = t; i < 64 * K; i += 256) {
        int n = i / K, k = i - n * K;
        int ng = base + n;
        float v = 0.f;
        if (ng < nNodes) {
            if (k < SELF) v = self[(size_t)ng * SELF + k];
            else {
                float c = cnt[ng];
                v = agg[(size_t)ng * SELF + (k - SELF)] / fmaxf(c, 1.0f);
            }
        }
        Xs[k * NP + n] = v;
    }
    __syncthreads();

    const int node = t & 63;
    const int j0 = (t >> 6) * 32;

    float acc[32];
    #pragma unroll
    for (int j = 0; j < 32; j++) acc[j] = b[j0 + j];

    #pragma unroll 4
    for (int k = 0; k < K; k++) {
        float xv = Xs[k * NP + node];
        const float4* wrow = (const float4*)(Ws + k * 128 + j0);
        #pragma unroll
        for (int jj = 0; jj < 8; jj++) {
            float4 w = wrow[jj];
            acc[4 * jj + 0] = fmaf(xv, w.x, acc[4 * jj + 0]);
            acc[4 * jj + 1] = fmaf(xv, w.y, acc[4 * jj + 1]);
            acc[4 * jj + 2] = fmaf(xv, w.z, acc[4 * jj + 2]);
            acc[4 * jj + 3] = fmaf(xv, w.w, acc[4 * jj + 3]);
        }
    }
    __syncthreads();   // done reading Ws; reuse for staging

    // Stage results [node][132] for coalesced write-back
    float* Rs = Ws;
    #pragma unroll
    for (int jj = 0; jj < 32; jj++)
        Rs[node * 132 + j0 + jj] = sigmoidf_(acc[jj]);
    __syncthreads();

    const float4* Rs4 = (const float4*)Rs;
    float4* out4 = (float4*)out;
    for (int i = t; i < 64 * 32; i += 256) {
        int n = i >> 5, j4 = i & 31;
        int ng = base + n;
        if (ng < nNodes) out4[(size_t)ng * 32 + j4] = Rs4[n * 33 + j4];
    }
}

// -------- fused MLP: out = relu(h2 @ Wm1 + bm1) @ Wm2 + bm2 --------
// 64 nodes / block, 256 threads.
__global__ void __launch_bounds__(256) mlp_kernel(
    const float* __restrict__ h2,     // [N, 128]
    const float* __restrict__ Wm1,    // [128, 256]
    const float* __restrict__ bm1,    // [256]
    const float* __restrict__ Wm2,    // [256, 40]
    const float* __restrict__ bm2,    // [40]
    float* __restrict__ out,          // [N, 40]
    int nNodes)
{
    extern __shared__ float smf[];
    float* Xs  = smf;                    // 128 * 65  (transposed h2 tile)
    float* hm  = smf + 128 * 65;         // 256 * 65  (transposed hidden)
    float* Wsh = smf + 128 * 65 + 256 * 65;  // 32768 floats (Wm1), later Wm2

    const int t = threadIdx.x;
    const int base = blockIdx.x * 64;

    // Load Wm1
    {
        const float4* Wg = (const float4*)Wm1;
        float4* Ws4 = (float4*)Wsh;
        for (int i = t; i < 128 * 64; i += 256) Ws4[i] = Wg[i];
    }
    // Build Xs[k][n] from h2
    for (int i = t; i < 64 * 128; i += 256) {
        int n = i >> 7, k = i & 127;
        int ng = base + n;
        Xs[k * 65 + n] = (ng < nNodes) ? h2[(size_t)ng * 128 + k] : 0.f;
    }
    __syncthreads();

    const int node = t & 63;
    const int jq = t >> 6;   // 0..3

    // Phase A: hm = relu(Xs @ Wm1 + bm1); thread computes 64 of 256 outputs
    {
        const int j0 = jq * 64;
        float acc[64];
        #pragma unroll
        for (int j = 0; j < 64; j++) acc[j] = bm1[j0 + j];
        #pragma unroll 2
        for (int k = 0; k < 128; k++) {
            float xv = Xs[k * 65 + node];
            const float4* wrow = (const float4*)(Wsh + k * 256 + j0);
            #pragma unroll
            for (int jj = 0; jj < 16; jj++) {
                float4 w = wrow[jj];
                acc[4 * jj + 0] = fmaf(xv, w.x, acc[4 * jj + 0]);
                acc[4 * jj + 1] = fmaf(xv, w.y, acc[4 * jj + 1]);
                acc[4 * jj + 2] = fmaf(xv, w.z, acc[4 * jj + 2]);
                acc[4 * jj + 3] = fmaf(xv, w.w, acc[4 * jj + 3]);
            }
        }
        #pragma unroll
        for (int jj = 0; jj < 64; jj++)
            hm[(j0 + jj) * 65 + node] = fmaxf(acc[jj], 0.f);
    }
    __syncthreads();   // hm complete; Wsh free to reuse

    // Load Wm2 into Wsh
    {
        const float4* Wg = (const float4*)Wm2;
        float4* Ws4 = (float4*)Wsh;
        for (int i = t; i < 256 * 10; i += 256) Ws4[i] = Wg[i];
    }
    __syncthreads();

    // Phase B: out = hm @ Wm2 + bm2; thread computes 10 of 40 outputs
    {
        const int j0 = jq * 10;
        float acc[10];
        #pragma unroll
        for (int j = 0; j < 10; j++) acc[j] = bm2[j0 + j];
        #pragma unroll 4
        for (int k = 0; k < 256; k++) {
            float xv = hm[k * 65 + node];
            const float2* wrow = (const float2*)(Wsh + k * 40 + j0);
            #pragma unroll
            for (int jj = 0; jj < 5; jj++) {
                float2 w = wrow[jj];
                acc[2 * jj + 0] = fmaf(xv, w.x, acc[2 * jj + 0]);
                acc[2 * jj + 1] = fmaf(xv, w.y, acc[2 * jj + 1]);
            }
        }
        // Stage into Xs region (no longer needed), [node][40]
        #pragma unroll
        for (int jj = 0; jj < 10; jj++)
            Xs[node * 40 + j0 + jj] = acc[jj];
    }
    __syncthreads();

    const float4* Rs4 = (const float4*)Xs;
    float4* out4 = (float4*)out;
    for (int i = t; i < 64 * 10; i += 256) {
        int n = i / 10, j4 = i - n * 10;
        int ng = base + n;
        if (ng < nNodes) out4[(size_t)ng * 10 + j4] = Rs4[n * 10 + j4];
    }
}

// -------- launch --------
extern "C" void kernel_launch(void* const* d_in, const int* in_sizes, int n_in,
                              void* d_out, int out_size)
{
    const float* feat = (const float*)d_in[0];
    const int*   ei   = (const int*)d_in[1];     // int32 (JAX x64 disabled)
    const float* W1  = (const float*)d_in[2];
    const float* b1  = (const float*)d_in[3];
    const float* W2  = (const float*)d_in[4];
    const float* b2  = (const float*)d_in[5];
    const float* Wm1 = (const float*)d_in[6];
    const float* bm1 = (const float*)d_in[7];
    const float* Wm2 = (const float*)d_in[8];
    const float* bm2 = (const float*)d_in[9];
    float* out = (float*)d_out;

    const int N = in_sizes[0] / 64;     // 100000
    const int E = in_sizes[1] / 2;      // 1600000

    float *agg, *cnt, *h1, *h2;
    cudaGetSymbolAddress((void**)&agg, g_agg);
    cudaGetSymbolAddress((void**)&cnt, g_cnt);
    cudaGetSymbolAddress((void**)&h1,  g_h1);
    cudaGetSymbolAddress((void**)&h2,  g_h2);

    const int SM_C1  = (128 * 65 + 128 * 128) * 4;                 //  98,816 B
    const int SM_C2  = (256 * 65 + 256 * 128) * 4;                 // 197,632 B
    const int SM_MLP = (128 * 65 + 256 * 65 + 128 * 256) * 4;      // 230,912 B
    cudaFuncSetAttribute(combine_kernel<128>, cudaFuncAttributeMaxDynamicSharedMemorySize, SM_C1);
    cudaFuncSetAttribute(combine_kernel<256>, cudaFuncAttributeMaxDynamicSharedMemorySize, SM_C2);
    cudaFuncSetAttribute(mlp_kernel,          cudaFuncAttributeMaxDynamicSharedMemorySize, SM_MLP);

    const int nodeBlocks = (N + 63) / 64;

    // Layer 1
    {
        int n4 = (N * 64) / 4;
        zero_kernel<<<4096, 256>>>((float4*)agg, n4);
        zero_kernel<<<256, 256>>>((float4*)cnt, N / 4);
        long long tot = (long long)E * 4;
        int blocks = (int)((tot + 255) / 256);
        scatter_kernel<64><<<blocks, 256>>>(ei, feat, agg, cnt, E, N, 1);
        combine_kernel<128><<<nodeBlocks, 256, SM_C1>>>(feat, agg, cnt, W1, b1, h1, N);
    }
    // Layer 2
    {
        int n4 = (N * 128) / 4;
        zero_kernel<<<4096, 256>>>((float4*)agg, n4);
        long long tot = (long long)E * 8;
        int blocks = (int)((tot + 255) / 256);
        scatter_kernel<128><<<blocks, 256>>>(ei, h1, agg, cnt, E, N, 0);
        combine_kernel<256><<<nodeBlocks, 256, SM_C2>>>(h1, agg, cnt, W2, b2, h2, N);
    }
    // MLP
    mlp_kernel<<<nodeBlocks, 256, SM_MLP>>>(h2, Wm1, bm1, Wm2, bm2, out, N);
}

// round 5
// speedup vs baseline: 1.1614x; 1.1614x over previous
#include <cuda_runtime.h>
#include <math.h>

#define NN 100000
#define EE 1600000

// -------- scratch (device globals; no allocation allowed) --------
__device__ float g_cnt[NN];
__device__ float g_agg[(size_t)NN * 128];
__device__ float g_h1[(size_t)NN * 128];
__device__ float g_h2[(size_t)NN * 128];
__device__ float g_hmT[(size_t)NN * 256];   // hidden MLP layer, TRANSPOSED [256][NN]

// -------- helpers --------
__device__ __forceinline__ void red_add_v4(float* addr, float4 v) {
    asm volatile("red.global.add.v4.f32 [%0], {%1,%2,%3,%4};"
                 :: "l"(addr), "f"(v.x), "f"(v.y), "f"(v.z), "f"(v.w) : "memory");
}
__device__ __forceinline__ void red_add_f32(float* addr, float v) {
    asm volatile("red.global.add.f32 [%0], %1;" :: "l"(addr), "f"(v) : "memory");
}
__device__ __forceinline__ float sigmoidf_(float x) {
    return 1.0f / (1.0f + __expf(-x));
}
__device__ __forceinline__ void fma4(float4& a, float s, const float4& x) {
    a.x = fmaf(s, x.x, a.x); a.y = fmaf(s, x.y, a.y);
    a.z = fmaf(s, x.z, a.z); a.w = fmaf(s, x.w, a.w);
}

// -------- zero --------
__global__ void zero_kernel(float4* __restrict__ p, int n4) {
    int i = blockIdx.x * blockDim.x + threadIdx.x;
    int stride = gridDim.x * blockDim.x;
    float4 z = make_float4(0.f, 0.f, 0.f, 0.f);
    for (; i < n4; i += stride) p[i] = z;
}

// -------- edge scatter: per-thread = (edge, 16-float chunk); edge_index is int32 --------
template<int D>
__global__ void __launch_bounds__(256) scatter_kernel(
    const int* __restrict__ ei,         // [2, E] int32
    const float* __restrict__ x,        // [N, D]
    float* __restrict__ agg,            // [N, D]
    float* __restrict__ cnt,            // [N]
    int E, int nNodes, int doCnt)
{
    const int CH = D / 16;
    long long tid = (long long)blockIdx.x * blockDim.x + threadIdx.x;
    long long e = tid / CH;
    int c = (int)(tid - e * CH);
    if (e >= E) return;
    int s = ei[e];
    int d = ei[(long long)E + e];
    if ((unsigned)s >= (unsigned)nNodes || (unsigned)d >= (unsigned)nNodes) return;
    const float4* src = (const float4*)(x + (size_t)s * D + c * 16);
    float* dst = agg + (size_t)d * D + c * 16;
    float4 a = src[0], b = src[1], cc = src[2], dd = src[3];
    red_add_v4(dst + 0, a);
    red_add_v4(dst + 4, b);
    red_add_v4(dst + 8, cc);
    red_add_v4(dst + 12, dd);
    if (doCnt && c == 0) red_add_f32(cnt + d, 1.0f);
}

// ============================================================================
// combine: X = concat(self, agg/max(cnt,1)) [K]; out = sigmoid(X @ W + b), 128 outs
// 64 nodes/block, 256 threads. Register tile: 4 nodes x 8 outs per thread.
// K processed in chunks of 128 so smem stays at 96KB -> 2 blocks/SM.
// ============================================================================
template<int K>
__global__ void __launch_bounds__(256) combine_kernel(
    const float* __restrict__ self,   // [N, K/2]
    const float* __restrict__ agg,    // [N, K/2]
    const float* __restrict__ cnt,    // [N]
    const float* __restrict__ W,      // [K, 128] row-major
    const float* __restrict__ b,      // [128]
    float* __restrict__ out,          // [N, 128]
    int nNodes)
{
    constexpr int SELF = K / 2;
    constexpr int NCH = K / 128;
    extern __shared__ float smf[];
    float* Xs = smf;               // [128][64]  (k-major, node minor)
    float* Ws = smf + 128 * 64;    // [128][128]

    const int t = threadIdx.x;
    const int base = blockIdx.x * 64;
    const int ng = t & 15;         // node group (4 nodes)
    const int og = t >> 4;         // out group (8 outs)
    const int n0 = ng * 4;
    const int j0 = og * 8;

    float4 acc[8];
    #pragma unroll
    for (int j = 0; j < 8; ++j) {
        float bv = b[j0 + j];
        acc[j] = make_float4(bv, bv, bv, bv);
    }

    for (int c = 0; c < NCH; ++c) {
        if (c) __syncthreads();
        // load W chunk (rows c*128 .. c*128+127)
        {
            const float4* Wg = (const float4*)(W + (size_t)c * 128 * 128);
            float4* Ws4 = (float4*)Ws;
            for (int i = t; i < 128 * 32; i += 256) Ws4[i] = Wg[i];
        }
        // build X chunk, transposed: Xs[kk][n]
        for (int i = t; i < 64 * 128; i += 256) {
            int n = i >> 7, kk = i & 127;
            int kg = c * 128 + kk;
            int ngl = base + n;
            float v = 0.f;
            if (ngl < nNodes) {
                if (kg < SELF) v = self[(size_t)ngl * SELF + kg];
                else v = agg[(size_t)ngl * SELF + (kg - SELF)] / fmaxf(cnt[ngl], 1.0f);
            }
            Xs[kk * 64 + n] = v;
        }
        __syncthreads();

        #pragma unroll 4
        for (int kk = 0; kk < 128; ++kk) {
            float4 x4 = *(const float4*)(Xs + kk * 64 + n0);
            float4 wa = *(const float4*)(Ws + kk * 128 + j0);
            float4 wb = *(const float4*)(Ws + kk * 128 + j0 + 4);
            fma4(acc[0], wa.x, x4); fma4(acc[1], wa.y, x4);
            fma4(acc[2], wa.z, x4); fma4(acc[3], wa.w, x4);
            fma4(acc[4], wb.x, x4); fma4(acc[5], wb.y, x4);
            fma4(acc[6], wb.z, x4); fma4(acc[7], wb.w, x4);
        }
    }
    __syncthreads();   // done reading Ws; reuse as staging

    // stage Rs[node][132] with sigmoid
    float* Rs = Ws;
    #pragma unroll
    for (int j = 0; j < 8; ++j) {
        Rs[(n0 + 0) * 132 + j0 + j] = sigmoidf_(acc[j].x);
        Rs[(n0 + 1) * 132 + j0 + j] = sigmoidf_(acc[j].y);
        Rs[(n0 + 2) * 132 + j0 + j] = sigmoidf_(acc[j].z);
        Rs[(n0 + 3) * 132 + j0 + j] = sigmoidf_(acc[j].w);
    }
    __syncthreads();

    const float4* Rs4 = (const float4*)Rs;
    float4* out4 = (float4*)out;
    for (int i = t; i < 64 * 32; i += 256) {
        int n = i >> 5, q = i & 31;
        int ngl = base + n;
        if (ngl < nNodes) out4[(size_t)ngl * 32 + q] = Rs4[n * 33 + q];
    }
}

// ============================================================================
// mlp1: hmT = relu(h2 @ Wm1 + bm1), written TRANSPOSED: hmT[j][n], j in [0,256)
// 64 nodes/block, 256 threads, tile 4n x 8o, two N-passes of 128 cols.
// ============================================================================
__global__ void __launch_bounds__(256) mlp1_kernel(
    const float* __restrict__ h2,     // [N, 128]
    const float* __restrict__ Wm1,    // [128, 256]
    const float* __restrict__ bm1,    // [256]
    float* __restrict__ hmT,          // [256][N]
    int nNodes)
{
    extern __shared__ float smf[];
    float* Xs = smf;               // [128][64]
    float* Ws = smf + 128 * 64;    // [128][128]

    const int t = threadIdx.x;
    const int base = blockIdx.x * 64;
    const int ng = t & 15;
    const int og = t >> 4;
    const int n0 = ng * 4;
    const int j0 = og * 8;

    // build Xs[kk][n] from h2
    for (int i = t; i < 64 * 128; i += 256) {
        int n = i >> 7, kk = i & 127;
        int ngl = base + n;
        Xs[kk * 64 + n] = (ngl < nNodes) ? h2[(size_t)ngl * 128 + kk] : 0.f;
    }

    for (int pass = 0; pass < 2; ++pass) {
        __syncthreads();   // Xs ready / previous pass done reading Ws
        // load Wm1 column chunk: Ws[kk][j] = Wm1[kk][pass*128 + j]
        {
            const float4* Wg = (const float4*)Wm1;
            float4* Ws4 = (float4*)Ws;
            for (int i = t; i < 128 * 32; i += 256) {
                int kk = i >> 5, q = i & 31;
                Ws4[kk * 32 + q] = Wg[kk * 64 + pass * 32 + q];
            }
        }
        __syncthreads();

        float4 acc[8];
        #pragma unroll
        for (int j = 0; j < 8; ++j) {
            float bv = bm1[pass * 128 + j0 + j];
            acc[j] = make_float4(bv, bv, bv, bv);
        }
        #pragma unroll 4
        for (int kk = 0; kk < 128; ++kk) {
            float4 x4 = *(const float4*)(Xs + kk * 64 + n0);
            float4 wa = *(const float4*)(Ws + kk * 128 + j0);
            float4 wb = *(const float4*)(Ws + kk * 128 + j0 + 4);
            fma4(acc[0], wa.x, x4); fma4(acc[1], wa.y, x4);
            fma4(acc[2], wa.z, x4); fma4(acc[3], wa.w, x4);
            fma4(acc[4], wb.x, x4); fma4(acc[5], wb.y, x4);
            fma4(acc[6], wb.z, x4); fma4(acc[7], wb.w, x4);
        }

        // store transposed with relu
        int nglob = base + n0;
        if (nglob + 3 < nNodes) {
            #pragma unroll
            for (int j = 0; j < 8; ++j) {
                float4 v = acc[j];
                v.x = fmaxf(v.x, 0.f); v.y = fmaxf(v.y, 0.f);
                v.z = fmaxf(v.z, 0.f); v.w = fmaxf(v.w, 0.f);
                *(float4*)(hmT + (size_t)(pass * 128 + j0 + j) * NN + nglob) = v;
            }
        } else {
            #pragma unroll
            for (int j = 0; j < 8; ++j) {
                float vv[4] = {acc[j].x, acc[j].y, acc[j].z, acc[j].w};
                size_t rowb = (size_t)(pass * 128 + j0 + j) * NN;
                for (int i2 = 0; i2 < 4; ++i2)
                    if (nglob + i2 < nNodes)
                        hmT[rowb + nglob + i2] = fmaxf(vv[i2], 0.f);
            }
        }
    }
}

// ============================================================================
// mlp2: out = hmT^T @ Wm2 + bm2  (K=256, NOUT=40)
// 256 nodes/block, 256 threads, tile 4n x 10o. hmT read coalesced via LDG.128.
// ============================================================================
__global__ void __launch_bounds__(256) mlp2_kernel(
    const float* __restrict__ hmT,    // [256][N]
    const float* __restrict__ Wm2,    // [256, 40]
    const float* __restrict__ bm2,    // [40]
    float* __restrict__ out,          // [N, 40]
    int nNodes)
{
    extern __shared__ float smf[];
    float* Ws = smf;                  // [256][40]
    float* Rs = smf + 256 * 40;       // [256][44]

    const int t = threadIdx.x;
    const int base = blockIdx.x * 256;
    const int ng = t & 63;
    const int og = t >> 6;            // 0..3, 10 outs each
    const int n0 = base + ng * 4;
    const int j0 = og * 10;

    // load Wm2 (10240 floats, contiguous)
    {
        const float4* Wg = (const float4*)Wm2;
        float4* Ws4 = (float4*)Ws;
        for (int i = t; i < 2560; i += 256) Ws4[i] = Wg[i];
    }
    __syncthreads();

    float4 acc[10];
    #pragma unroll
    for (int j = 0; j < 10; ++j) {
        float bv = bm2[j0 + j];
        acc[j] = make_float4(bv, bv, bv, bv);
    }

    if (n0 + 3 < nNodes) {
        #pragma unroll 2
        for (int k = 0; k < 256; ++k) {
            float4 x4 = *(const float4*)(hmT + (size_t)k * NN + n0);
            const float2* wr = (const float2*)(Ws + k * 40 + j0);
            float2 w0 = wr[0], w1 = wr[1], w2 = wr[2], w3 = wr[3], w4 = wr[4];
            fma4(acc[0], w0.x, x4); fma4(acc[1], w0.y, x4);
            fma4(acc[2], w1.x, x4); fma4(acc[3], w1.y, x4);
            fma4(acc[4], w2.x, x4); fma4(acc[5], w2.y, x4);
            fma4(acc[6], w3.x, x4); fma4(acc[7], w3.y, x4);
            fma4(acc[8], w4.x, x4); fma4(acc[9], w4.y, x4);
        }
    } else {
        for (int k = 0; k < 256; ++k) {
            float4 x4;
            const float* row = hmT + (size_t)k * NN;
            x4.x = (n0 + 0 < nNodes) ? row[n0 + 0] : 0.f;
            x4.y = (n0 + 1 < nNodes) ? row[n0 + 1] : 0.f;
            x4.z = (n0 + 2 < nNodes) ? row[n0 + 2] : 0.f;
            x4.w = (n0 + 3 < nNodes) ? row[n0 + 3] : 0.f;
            const float2* wr = (const float2*)(Ws + k * 40 + j0);
            float2 w0 = wr[0], w1 = wr[1], w2 = wr[2], w3 = wr[3], w4 = wr[4];
            fma4(acc[0], w0.x, x4); fma4(acc[1], w0.y, x4);
            fma4(acc[2], w1.x, x4); fma4(acc[3], w1.y, x4);
            fma4(acc[4], w2.x, x4); fma4(acc[5], w2.y, x4);
            fma4(acc[6], w3.x, x4); fma4(acc[7], w3.y, x4);
            fma4(acc[8], w4.x, x4); fma4(acc[9], w4.y, x4);
        }
    }

    // stage Rs[node_local][44] then coalesced write-back
    int nl = ng * 4;
    #pragma unroll
    for (int j = 0; j < 10; ++j) {
        Rs[(nl + 0) * 44 + j0 + j] = acc[j].x;
        Rs[(nl + 1) * 44 + j0 + j] = acc[j].y;
        Rs[(nl + 2) * 44 + j0 + j] = acc[j].z;
        Rs[(nl + 3) * 44 + j0 + j] = acc[j].w;
    }
    __syncthreads();

    const float4* Rs4 = (const float4*)Rs;
    float4* out4 = (float4*)out;
    for (int i = t; i < 256 * 10; i += 256) {
        int n = i / 10, q = i - n * 10;
        int ngl = base + n;
        if (ngl < nNodes) out4[(size_t)ngl * 10 + q] = Rs4[n * 11 + q];
    }
}

// -------- launch --------
extern "C" void kernel_launch(void* const* d_in, const int* in_sizes, int n_in,
                              void* d_out, int out_size)
{
    const float* feat = (const float*)d_in[0];
    const int*   ei   = (const int*)d_in[1];     // int32 (JAX x64 disabled)
    const float* W1  = (const float*)d_in[2];
    const float* b1  = (const float*)d_in[3];
    const float* W2  = (const float*)d_in[4];
    const float* b2  = (const float*)d_in[5];
    const float* Wm1 = (const float*)d_in[6];
    const float* bm1 = (const float*)d_in[7];
    const float* Wm2 = (const float*)d_in[8];
    const float* bm2 = (const float*)d_in[9];
    float* out = (float*)d_out;

    const int N = in_sizes[0] / 64;     // 100000
    const int E = in_sizes[1] / 2;      // 1600000

    float *agg, *cnt, *h1, *h2, *hmT;
    cudaGetSymbolAddress((void**)&agg, g_agg);
    cudaGetSymbolAddress((void**)&cnt, g_cnt);
    cudaGetSymbolAddress((void**)&h1,  g_h1);
    cudaGetSymbolAddress((void**)&h2,  g_h2);
    cudaGetSymbolAddress((void**)&hmT, g_hmT);

    const int SM_GEMM = (128 * 64 + 128 * 128) * 4;   // 98,304 B
    const int SM_MLP2 = (256 * 40 + 256 * 44) * 4;    // 86,016 B
    cudaFuncSetAttribute(combine_kernel<128>, cudaFuncAttributeMaxDynamicSharedMemorySize, SM_GEMM);
    cudaFuncSetAttribute(combine_kernel<256>, cudaFuncAttributeMaxDynamicSharedMemorySize, SM_GEMM);
    cudaFuncSetAttribute(mlp1_kernel,         cudaFuncAttributeMaxDynamicSharedMemorySize, SM_GEMM);
    cudaFuncSetAttribute(mlp2_kernel,         cudaFuncAttributeMaxDynamicSharedMemorySize, SM_MLP2);

    const int nodeBlocks = (N + 63) / 64;        // 1563
    const int mlp2Blocks = (N + 255) / 256;      // 391

    // Layer 1
    {
        int n4 = (N * 64) / 4;
        zero_kernel<<<4096, 256>>>((float4*)agg, n4);
        zero_kernel<<<256, 256>>>((float4*)cnt, N / 4);
        long long tot = (long long)E * 4;
        int blocks = (int)((tot + 255) / 256);
        scatter_kernel<64><<<blocks, 256>>>(ei, feat, agg, cnt, E, N, 1);
        combine_kernel<128><<<nodeBlocks, 256, SM_GEMM>>>(feat, agg, cnt, W1, b1, h1, N);
    }
    // Layer 2
    {
        int n4 = (N * 128) / 4;
        zero_kernel<<<4096, 256>>>((float4*)agg, n4);
        long long tot = (long long)E * 8;
        int blocks = (int)((tot + 255) / 256);
        scatter_kernel<128><<<blocks, 256>>>(ei, h1, agg, cnt, E, N, 0);
        combine_kernel<256><<<nodeBlocks, 256, SM_GEMM>>>(h1, agg, cnt, W2, b2, h2, N);
    }
    // MLP
    mlp1_kernel<<<nodeBlocks, 256, SM_GEMM>>>(h2, Wm1, bm1, hmT, N);
    mlp2_kernel<<<mlp2Blocks, 256, SM_MLP2>>>(hmT, Wm2, bm2, out, N);
}

// round 6
// speedup vs baseline: 1.2503x; 1.0766x over previous
#include <cuda_runtime.h>
#include <math.h>

#define NN 100000
#define EE 1600000

// -------- scratch (device globals; no allocation allowed) --------
__device__ float g_cnt[NN];
__device__ float g_agg[(size_t)NN * 128];
__device__ float g_h1[(size_t)NN * 128];
__device__ float g_h2[(size_t)NN * 128];
__device__ float g_hmT[(size_t)NN * 256];   // hidden MLP layer, TRANSPOSED [256][N]

// -------- helpers --------
__device__ __forceinline__ void red_add_v4(float* addr, float4 v) {
    asm volatile("red.global.add.v4.f32 [%0], {%1,%2,%3,%4};"
                 :: "l"(addr), "f"(v.x), "f"(v.y), "f"(v.z), "f"(v.w) : "memory");
}
__device__ __forceinline__ void red_add_f32(float* addr, float v) {
    asm volatile("red.global.add.f32 [%0], %1;" :: "l"(addr), "f"(v) : "memory");
}
__device__ __forceinline__ float sigmoidf_(float x) {
    return 1.0f / (1.0f + __expf(-x));
}
__device__ __forceinline__ void fma4(float4& a, float s, const float4& x) {
    a.x = fmaf(s, x.x, a.x); a.y = fmaf(s, x.y, a.y);
    a.z = fmaf(s, x.z, a.z); a.w = fmaf(s, x.w, a.w);
}

// -------- zero --------
__global__ void zero_kernel(float4* __restrict__ p, int n4) {
    int i = blockIdx.x * blockDim.x + threadIdx.x;
    int stride = gridDim.x * blockDim.x;
    float4 z = make_float4(0.f, 0.f, 0.f, 0.f);
    for (; i < n4; i += stride) p[i] = z;
}

// -------- cnt -> 1/max(cnt,1) --------
__global__ void invcnt_kernel(float* __restrict__ cnt, int n) {
    int i = blockIdx.x * blockDim.x + threadIdx.x;
    if (i < n) cnt[i] = 1.0f / fmaxf(cnt[i], 1.0f);
}

// -------- edge scatter: per-thread = (edge, 16-float chunk); edge_index is int32 --------
template<int D>
__global__ void __launch_bounds__(256) scatter_kernel(
    const int* __restrict__ ei,         // [2, E] int32
    const float* __restrict__ x,        // [N, D]
    float* __restrict__ agg,            // [N, D]
    float* __restrict__ cnt,            // [N]
    int E, int nNodes, int doCnt)
{
    const int CH = D / 16;
    long long tid = (long long)blockIdx.x * blockDim.x + threadIdx.x;
    long long e = tid / CH;
    int c = (int)(tid - e * CH);
    if (e >= E) return;
    int s = ei[e];
    int d = ei[(long long)E + e];
    if ((unsigned)s >= (unsigned)nNodes || (unsigned)d >= (unsigned)nNodes) return;
    const float4* src = (const float4*)(x + (size_t)s * D + c * 16);
    float* dst = agg + (size_t)d * D + c * 16;
    float4 a = src[0], b = src[1], cc = src[2], dd = src[3];
    red_add_v4(dst + 0, a);
    red_add_v4(dst + 4, b);
    red_add_v4(dst + 8, cc);
    red_add_v4(dst + 12, dd);
    if (doCnt && c == 0) red_add_f32(cnt + d, 1.0f);
}

// ============================================================================
// combine: X = concat(self, agg*invc) [K]; out = sigmoid(X @ W + b), 128 outs
// 64 nodes/block, 256 threads. Tile: 4 strided nodes {ng,ng+16,ng+32,ng+48} x 8 outs.
// Xs padded stride 65 (conflict-free build + conflict-free scalar x loads).
// W in 64-row chunks -> smem 66KB (K=128, 3 blocks/SM) / 99KB (K=256, 2 blocks/SM).
// ============================================================================
template<int K>
__global__ void __launch_bounds__(256) combine_kernel(
    const float* __restrict__ self,   // [N, K/2]
    const float* __restrict__ agg,    // [N, K/2]
    const float* __restrict__ invc,   // [N]  (reciprocal counts)
    const float* __restrict__ W,      // [K, 128] row-major
    const float* __restrict__ b,      // [128]
    float* __restrict__ out,          // [N, 128]
    int nNodes)
{
    constexpr int SELF = K / 2;
    constexpr int NCH = K / 64;
    constexpr int SHIFT = (K == 128) ? 7 : 8;
    extern __shared__ float smf[];
    float* Xs = smf;                // [K][65]
    float* Ws = smf + K * 65;       // [64][128]

    const int t = threadIdx.x;
    const int base = blockIdx.x * 64;
    const int ng = t & 15;
    const int og = t >> 4;
    const int j0 = og * 8;

    // build X, transposed, pad 65: lanes at consecutive kk -> coalesced LDG, conflict-free STS
    for (int i = t; i < 64 * K; i += 256) {
        int n = i >> SHIFT, kk = i & (K - 1);
        int ngl = base + n;
        float v = 0.f;
        if (ngl < nNodes) {
            if (kk < SELF) v = self[(size_t)ngl * SELF + kk];
            else v = agg[(size_t)ngl * SELF + (kk - SELF)] * invc[ngl];
        }
        Xs[kk * 65 + n] = v;
    }

    float4 acc[8];
    #pragma unroll
    for (int j = 0; j < 8; ++j) {
        float bv = b[j0 + j];
        acc[j] = make_float4(bv, bv, bv, bv);
    }

    for (int c = 0; c < NCH; ++c) {
        __syncthreads();   // Xs ready (c=0) / prev chunk done reading Ws (c>0)
        {
            const float4* Wg = (const float4*)(W + (size_t)c * 64 * 128);
            float4* Ws4 = (float4*)Ws;
            for (int i = t; i < 64 * 32; i += 256) Ws4[i] = Wg[i];
        }
        __syncthreads();
        const float* Xc = Xs + c * 64 * 65;
        #pragma unroll 4
        for (int kk = 0; kk < 64; ++kk) {
            const float* xr = Xc + kk * 65 + ng;
            float4 x4 = make_float4(xr[0], xr[16], xr[32], xr[48]);
            float4 wa = *(const float4*)(Ws + kk * 128 + j0);
            float4 wb = *(const float4*)(Ws + kk * 128 + j0 + 4);
            fma4(acc[0], wa.x, x4); fma4(acc[1], wa.y, x4);
            fma4(acc[2], wa.z, x4); fma4(acc[3], wa.w, x4);
            fma4(acc[4], wb.x, x4); fma4(acc[5], wb.y, x4);
            fma4(acc[6], wb.z, x4); fma4(acc[7], wb.w, x4);
        }
    }
    __syncthreads();   // all reads of Xs/Ws done; reuse smem as staging

    float* Rs = smf;   // [64][132]
    #pragma unroll
    for (int j = 0; j < 8; ++j) {
        Rs[(ng +  0) * 132 + j0 + j] = sigmoidf_(acc[j].x);
        Rs[(ng + 16) * 132 + j0 + j] = sigmoidf_(acc[j].y);
        Rs[(ng + 32) * 132 + j0 + j] = sigmoidf_(acc[j].z);
        Rs[(ng + 48) * 132 + j0 + j] = sigmoidf_(acc[j].w);
    }
    __syncthreads();

    const float4* Rs4 = (const float4*)Rs;
    float4* out4 = (float4*)out;
    for (int i = t; i < 64 * 32; i += 256) {
        int n = i >> 5, q = i & 31;
        int ngl = base + n;
        if (ngl < nNodes) out4[(size_t)ngl * 32 + q] = Rs4[n * 33 + q];
    }
}

// ============================================================================
// mlp1: hmT = relu(h2 @ Wm1 + bm1), written TRANSPOSED: hmT[j][n], j in [0,256)
// 64 nodes/block, 256 threads. Same tile as combine. 2 N-passes x 2 K-chunks.
// smem 66KB -> 3 blocks/SM. hmT written via staging tile (coalesced float4).
// ============================================================================
__global__ void __launch_bounds__(256) mlp1_kernel(
    const float* __restrict__ h2,     // [N, 128]
    const float* __restrict__ Wm1,    // [128, 256]
    const float* __restrict__ bm1,    // [256]
    float* __restrict__ hmT,          // [256][N]
    int nNodes)
{
    extern __shared__ float smf[];
    float* Xs = smf;               // [128][65]
    float* Ws = smf + 128 * 65;    // [64][128]  (also reused as staging [128][64])

    const int t = threadIdx.x;
    const int base = blockIdx.x * 64;
    const int ng = t & 15;
    const int og = t >> 4;
    const int j0 = og * 8;

    // build Xs[kk][n] from h2
    for (int i = t; i < 64 * 128; i += 256) {
        int n = i >> 7, kk = i & 127;
        int ngl = base + n;
        Xs[kk * 65 + n] = (ngl < nNodes) ? h2[(size_t)ngl * 128 + kk] : 0.f;
    }

    for (int pass = 0; pass < 2; ++pass) {
        float4 acc[8];
        #pragma unroll
        for (int j = 0; j < 8; ++j) {
            float bv = bm1[pass * 128 + j0 + j];
            acc[j] = make_float4(bv, bv, bv, bv);
        }
        for (int c = 0; c < 2; ++c) {
            __syncthreads();   // Xs ready / staging of prev pass drained / prev chunk read
            {
                const float4* Wg = (const float4*)Wm1;
                float4* Ws4 = (float4*)Ws;
                for (int i = t; i < 64 * 32; i += 256) {
                    int kl = i >> 5, q = i & 31;
                    Ws4[kl * 32 + q] = Wg[(c * 64 + kl) * 64 + pass * 32 + q];
                }
            }
            __syncthreads();
            const float* Xc = Xs + c * 64 * 65;
            #pragma unroll 4
            for (int kk = 0; kk < 64; ++kk) {
                const float* xr = Xc + kk * 65 + ng;
                float4 x4 = make_float4(xr[0], xr[16], xr[32], xr[48]);
                float4 wa = *(const float4*)(Ws + kk * 128 + j0);
                float4 wb = *(const float4*)(Ws + kk * 128 + j0 + 4);
                fma4(acc[0], wa.x, x4); fma4(acc[1], wa.y, x4);
                fma4(acc[2], wa.z, x4); fma4(acc[3], wa.w, x4);
                fma4(acc[4], wb.x, x4); fma4(acc[5], wb.y, x4);
                fma4(acc[6], wb.z, x4); fma4(acc[7], wb.w, x4);
            }
        }
        __syncthreads();   // done reading Ws; reuse as staging [128][64]
        float* Rst = Ws;
        #pragma unroll
        for (int j = 0; j < 8; ++j) {
            Rst[(j0 + j) * 64 + ng +  0] = fmaxf(acc[j].x, 0.f);
            Rst[(j0 + j) * 64 + ng + 16] = fmaxf(acc[j].y, 0.f);
            Rst[(j0 + j) * 64 + ng + 32] = fmaxf(acc[j].z, 0.f);
            Rst[(j0 + j) * 64 + ng + 48] = fmaxf(acc[j].w, 0.f);
        }
        __syncthreads();

        if (base + 64 <= nNodes) {
            const float4* Rst4 = (const float4*)Rst;
            for (int i = t; i < 128 * 16; i += 256) {
                int j = i >> 4, q = i & 15;
                *(float4*)(hmT + (size_t)(pass * 128 + j) * nNodes + base + q * 4) = Rst4[j * 16 + q];
            }
        } else {
            for (int i = t; i < 128 * 64; i += 256) {
                int j = i >> 6, n = i & 63;
                if (base + n < nNodes)
                    hmT[(size_t)(pass * 128 + j) * nNodes + base + n] = Rst[j * 64 + n];
            }
        }
    }
}

// ============================================================================
// mlp2: out = hmT^T @ Wm2 + bm2  (K=256, NOUT=40)
// 256 nodes/block, 256 threads, tile 4n x 10o. hmT read coalesced via LDG.128.
// ============================================================================
__global__ void __launch_bounds__(256) mlp2_kernel(
    const float* __restrict__ hmT,    // [256][N]
    const float* __restrict__ Wm2,    // [256, 40]
    const float* __restrict__ bm2,    // [40]
    float* __restrict__ out,          // [N, 40]
    int nNodes)
{
    extern __shared__ float smf[];
    float* Ws = smf;                  // [256][40]
    float* Rs = smf + 256 * 40;       // [256][44]

    const int t = threadIdx.x;
    const int base = blockIdx.x * 256;
    const int ng = t & 63;
    const int og = t >> 6;            // 0..3, 10 outs each
    const int n0 = base + ng * 4;
    const int j0 = og * 10;

    {
        const float4* Wg = (const float4*)Wm2;
        float4* Ws4 = (float4*)Ws;
        for (int i = t; i < 2560; i += 256) Ws4[i] = Wg[i];
    }
    __syncthreads();

    float4 acc[10];
    #pragma unroll
    for (int j = 0; j < 10; ++j) {
        float bv = bm2[j0 + j];
        acc[j] = make_float4(bv, bv, bv, bv);
    }

    if (n0 + 3 < nNodes) {
        #pragma unroll 2
        for (int k = 0; k < 256; ++k) {
            float4 x4 = *(const float4*)(hmT + (size_t)k * nNodes + n0);
            const float2* wr = (const float2*)(Ws + k * 40 + j0);
            float2 w0 = wr[0], w1 = wr[1], w2 = wr[2], w3 = wr[3], w4 = wr[4];
            fma4(acc[0], w0.x, x4); fma4(acc[1], w0.y, x4);
            fma4(acc[2], w1.x, x4); fma4(acc[3], w1.y, x4);
            fma4(acc[4], w2.x, x4); fma4(acc[5], w2.y, x4);
            fma4(acc[6], w3.x, x4); fma4(acc[7], w3.y, x4);
            fma4(acc[8], w4.x, x4); fma4(acc[9], w4.y, x4);
        }
    } else {
        for (int k = 0; k < 256; ++k) {
            float4 x4;
            const float* row = hmT + (size_t)k * nNodes;
            x4.x = (n0 + 0 < nNodes) ? row[n0 + 0] : 0.f;
            x4.y = (n0 + 1 < nNodes) ? row[n0 + 1] : 0.f;
            x4.z = (n0 + 2 < nNodes) ? row[n0 + 2] : 0.f;
            x4.w = (n0 + 3 < nNodes) ? row[n0 + 3] : 0.f;
            const float2* wr = (const float2*)(Ws + k * 40 + j0);
            float2 w0 = wr[0], w1 = wr[1], w2 = wr[2], w3 = wr[3], w4 = wr[4];
            fma4(acc[0], w0.x, x4); fma4(acc[1], w0.y, x4);
            fma4(acc[2], w1.x, x4); fma4(acc[3], w1.y, x4);
            fma4(acc[4], w2.x, x4); fma4(acc[5], w2.y, x4);
            fma4(acc[6], w3.x, x4); fma4(acc[7], w3.y, x4);
            fma4(acc[8], w4.x, x4); fma4(acc[9], w4.y, x4);
        }
    }

    int nl = ng * 4;
    #pragma unroll
    for (int j = 0; j < 10; ++j) {
        Rs[(nl + 0) * 44 + j0 + j] = acc[j].x;
        Rs[(nl + 1) * 44 + j0 + j] = acc[j].y;
        Rs[(nl + 2) * 44 + j0 + j] = acc[j].z;
        Rs[(nl + 3) * 44 + j0 + j] = acc[j].w;
    }
    __syncthreads();

    const float4* Rs4 = (const float4*)Rs;
    float4* out4 = (float4*)out;
    for (int i = t; i < 256 * 10; i += 256) {
        int n = i / 10, q = i - n * 10;
        int ngl = base + n;
        if (ngl < nNodes) out4[(size_t)ngl * 10 + q] = Rs4[n * 11 + q];
    }
}

// -------- launch --------
extern "C" void kernel_launch(void* const* d_in, const int* in_sizes, int n_in,
                              void* d_out, int out_size)
{
    const float* feat = (const float*)d_in[0];
    const int*   ei   = (const int*)d_in[1];     // int32 (JAX x64 disabled)
    const float* W1  = (const float*)d_in[2];
    const float* b1  = (const float*)d_in[3];
    const float* W2  = (const float*)d_in[4];
    const float* b2  = (const float*)d_in[5];
    const float* Wm1 = (const float*)d_in[6];
    const float* bm1 = (const float*)d_in[7];
    const float* Wm2 = (const float*)d_in[8];
    const float* bm2 = (const float*)d_in[9];
    float* out = (float*)d_out;

    const int N = in_sizes[0] / 64;     // 100000
    const int E = in_sizes[1] / 2;      // 1600000

    float *agg, *cnt, *h1, *h2, *hmT;
    cudaGetSymbolAddress((void**)&agg, g_agg);
    cudaGetSymbolAddress((void**)&cnt, g_cnt);
    cudaGetSymbolAddress((void**)&h1,  g_h1);
    cudaGetSymbolAddress((void**)&h2,  g_h2);
    cudaGetSymbolAddress((void**)&hmT, g_hmT);

    const int SM_C1  = (128 * 65 + 64 * 128) * 4;   //  66,048 B -> 3 blocks/SM
    const int SM_C2  = (256 * 65 + 64 * 128) * 4;   //  99,328 B -> 2 blocks/SM
    const int SM_MLP1 = SM_C1;
    const int SM_MLP2 = (256 * 40 + 256 * 44) * 4;  //  86,016 B
    cudaFuncSetAttribute(combine_kernel<128>, cudaFuncAttributeMaxDynamicSharedMemorySize, SM_C1);
    cudaFuncSetAttribute(combine_kernel<256>, cudaFuncAttributeMaxDynamicSharedMemorySize, SM_C2);
    cudaFuncSetAttribute(mlp1_kernel,         cudaFuncAttributeMaxDynamicSharedMemorySize, SM_MLP1);
    cudaFuncSetAttribute(mlp2_kernel,         cudaFuncAttributeMaxDynamicSharedMemorySize, SM_MLP2);

    const int nodeBlocks = (N + 63) / 64;        // 1563
    const int mlp2Blocks = (N + 255) / 256;      // 391

    // Layer 1
    {
        int n4 = (N * 64) / 4;
        zero_kernel<<<4096, 256>>>((float4*)agg, n4);
        zero_kernel<<<256, 256>>>((float4*)cnt, N / 4);
        long long tot = (long long)E * 4;
        int blocks = (int)((tot + 255) / 256);
        scatter_kernel<64><<<blocks, 256>>>(ei, feat, agg, cnt, E, N, 1);
        invcnt_kernel<<<(N + 255) / 256, 256>>>(cnt, N);
        combine_kernel<128><<<nodeBlocks, 256, SM_C1>>>(feat, agg, cnt, W1, b1, h1, N);
    }
    // Layer 2
    {
        int n4 = (N * 128) / 4;
        zero_kernel<<<4096, 256>>>((float4*)agg, n4);
        long long tot = (long long)E * 8;
        int blocks = (int)((tot + 255) / 256);
        scatter_kernel<128><<<blocks, 256>>>(ei, h1, agg, cnt, E, N, 0);
        combine_kernel<256><<<nodeBlocks, 256, SM_C2>>>(h1, agg, cnt, W2, b2, h2, N);
    }
    // MLP
    mlp1_kernel<<<nodeBlocks, 256, SM_MLP1>>>(h2, Wm1, bm1, hmT, N);
    mlp2_kernel<<<mlp2Blocks, 256, SM_MLP2>>>(hmT, Wm2, bm2, out, N);
}